// round 2
// baseline (speedup 1.0000x reference)
#include <cuda_runtime.h>
#include <stdint.h>

// Problem constants (fixed by the dataset: B=4, H=376, W=1241, C=64)
#define BATCH   4
#define HH      376
#define WW      1241
#define CC      64
#define HW      (HH * WW)          // 466616  (divisible by 4)
#define NUM_PIX (BATCH * HW)       // 1866464
#define NPIX4   (NUM_PIX / 4)      // 466616

// Scratch: packed (depth_bits<<32 | point_index) per pixel. ~14.9 MB.
__device__ unsigned long long g_keys[NUM_PIX];
// Projection matrix P = K @ R @ V2P (3x4, row-major)
__device__ float g_P[12];

// ---------------------------------------------------------------------------
// Kernel 1: init keys to sentinel (4 keys / thread via 2x STG.128);
// thread 0 computes the projection matrix.
// ---------------------------------------------------------------------------
__global__ void k_init(const float* __restrict__ K) {
    int t = blockIdx.x * blockDim.x + threadIdx.x;
    if (t == 0) {
        // KR = K @ R, R = [[0,-1,0],[0,0,-1],[1,0,0]] (signed permutation):
        // (K@R)[i][0] = K[i][2]; (K@R)[i][1] = -K[i][0]; (K@R)[i][2] = -K[i][1]
        float KR[9];
        #pragma unroll
        for (int i = 0; i < 3; i++) {
            KR[i*3+0] =  K[i*3+2];
            KR[i*3+1] = -K[i*3+0];
            KR[i*3+2] = -K[i*3+1];
        }
        const float vv = 0.75f;
        const float xo = 0.375f;     // 0.75/2 + 0
        const float yo = -24.625f;   // 0.75/2 - 25
        const float zo = -24.625f;   // 0.75/2 - 25
        #pragma unroll
        for (int i = 0; i < 3; i++) {
            g_P[i*4+0] = KR[i*3+0] * vv;
            g_P[i*4+1] = KR[i*3+1] * vv;
            g_P[i*4+2] = KR[i*3+2] * vv;
            g_P[i*4+3] = KR[i*3+0]*xo + KR[i*3+1]*yo + KR[i*3+2]*zo;
        }
    }
    if (t < NPIX4) {
        ulonglong2 s;
        s.x = 0xFFFFFFFFFFFFFFFFull;
        s.y = 0xFFFFFFFFFFFFFFFFull;
        ulonglong2* p = reinterpret_cast<ulonglong2*>(g_keys) + 2 * t;
        p[0] = s;
        p[1] = s;
    }
}

// ---------------------------------------------------------------------------
// Kernel 2: per-point projection + 64-bit packed atomicMin z-buffer.
// Packing (depth_bits<<32 | index) reproduces the reference's
// "min depth, then min index among ties" semantics in one atomic.
// ---------------------------------------------------------------------------
__global__ void k_scatter(const int* __restrict__ coords, int N) {
    int i = blockIdx.x * blockDim.x + threadIdx.x;
    if (i >= N) return;
    int4 c = reinterpret_cast<const int4*>(coords)[i];  // (b, z, y, x)
    float x = (float)c.w;
    float y = (float)c.z;
    float z = (float)c.y;

    float p0 = fmaf(g_P[0], x, fmaf(g_P[1], y, fmaf(g_P[2],  z, g_P[3])));
    float p1 = fmaf(g_P[4], x, fmaf(g_P[5], y, fmaf(g_P[6],  z, g_P[7])));
    float d  = fmaf(g_P[8], x, fmaf(g_P[9], y, fmaf(g_P[10], z, g_P[11])));

    if (d > 1e-6f) {
        // IEEE division so floor boundaries match the fp32 reference
        int u = (int)floorf(__fdiv_rn(p0, d));
        int v = (int)floorf(__fdiv_rn(p1, d));
        if (u >= 0 && u < WW && v >= 0 && v < HH) {
            int pix = c.x * HW + v * WW + u;
            unsigned long long key =
                ((unsigned long long)__float_as_uint(d) << 32) | (unsigned int)i;
            atomicMin(&g_keys[pix], key);
        }
    }
}

// ---------------------------------------------------------------------------
// Kernel 3: gather, 4 consecutive pixels per thread. HW % 4 == 0, so a group
// never crosses a batch boundary and every plane store is a 16B-aligned
// STG.128 (float4 across the u dimension). Empty-pixel groups (the common
// case, ~2/3 of threads) write pure zeros with no feature loads.
// Output layout: [B*C*HW] features then [B*HW] inv_depth.
// ---------------------------------------------------------------------------
__global__ void k_gather(const float* __restrict__ feats, float* __restrict__ out) {
    int t = blockIdx.x * blockDim.x + threadIdx.x;
    if (t >= NPIX4) return;

    const ulonglong2* kp = reinterpret_cast<const ulonglong2*>(g_keys) + 2 * t;
    ulonglong2 ka = kp[0];
    ulonglong2 kb = kp[1];
    unsigned long long key[4] = { ka.x, ka.y, kb.x, kb.y };

    int p0 = t * 4;
    int b  = p0 / HW;
    int r  = p0 - b * HW;
    float* op = out + (size_t)b * CC * HW + r;

    const float4* frow[4];
    float4 inv;
    bool any = false;
    #pragma unroll
    for (int j = 0; j < 4; j++) {
        float iv;
        if (key[j] == 0xFFFFFFFFFFFFFFFFull) {
            iv = 0.0f;
            frow[j] = nullptr;
        } else {
            float d = __uint_as_float((unsigned int)(key[j] >> 32));
            iv = __fdiv_rn(1.0f, d);
            frow[j] = reinterpret_cast<const float4*>(
                feats + (size_t)(unsigned int)key[j] * CC);
            any = true;
        }
        (&inv.x)[j] = iv;
    }
    reinterpret_cast<float4*>(out + (size_t)NUM_PIX * CC)[t] = inv;

    if (!any) {
        const float4 z = make_float4(0.f, 0.f, 0.f, 0.f);
        #pragma unroll
        for (int c = 0; c < CC; c++) {
            *reinterpret_cast<float4*>(op + (size_t)c * HW) = z;
        }
    } else {
        #pragma unroll
        for (int q = 0; q < CC / 4; q++) {
            float4 f[4];
            #pragma unroll
            for (int j = 0; j < 4; j++) {
                f[j] = frow[j] ? __ldg(frow[j] + q) : make_float4(0.f, 0.f, 0.f, 0.f);
            }
            #pragma unroll
            for (int k = 0; k < 4; k++) {
                float4 o;
                o.x = (&f[0].x)[k];
                o.y = (&f[1].x)[k];
                o.z = (&f[2].x)[k];
                o.w = (&f[3].x)[k];
                *reinterpret_cast<float4*>(op + (size_t)(4 * q + k) * HW) = o;
            }
        }
    }
}

// ---------------------------------------------------------------------------
extern "C" void kernel_launch(void* const* d_in, const int* in_sizes, int n_in,
                              void* d_out, int out_size) {
    const float* feats  = (const float*)d_in[0];   // (N, 64) f32
    const int*   coords = (const int*)d_in[1];     // (N, 4)  i32
    const float* K      = (const float*)d_in[2];   // (3, 3)  f32

    int N = in_sizes[0] / CC;
    float* out = (float*)d_out;

    const int T = 256;
    k_init<<<(NPIX4 + T - 1) / T, T>>>(K);
    k_scatter<<<(N + T - 1) / T, T>>>(coords, N);
    k_gather<<<(NPIX4 + T - 1) / T, T>>>(feats, out);
}

// round 3
// speedup vs baseline: 1.0947x; 1.0947x over previous
#include <cuda_runtime.h>
#include <stdint.h>

// Problem constants (fixed by the dataset: B=4, H=376, W=1241, C=64)
#define BATCH   4
#define HH      376
#define WW      1241
#define CC      64
#define HW      (HH * WW)          // 466616  (divisible by 4)
#define NUM_PIX (BATCH * HW)       // 1866464
#define NPIX4   (NUM_PIX / 4)      // 466616

// Scratch: packed (depth_bits<<32 | point_index) per pixel (14.9 MB),
// then compacted winner index per pixel (7.5 MB).
__device__ unsigned long long g_keys[NUM_PIX];
__device__ int                g_widx[NUM_PIX];
// Projection matrix P = K @ R @ V2P (3x4, row-major)
__device__ float g_P[12];

// ---------------------------------------------------------------------------
// Kernel 1: init keys to sentinel; thread 0 computes the projection matrix.
// ---------------------------------------------------------------------------
__global__ void k_init(const float* __restrict__ K) {
    int t = blockIdx.x * blockDim.x + threadIdx.x;
    if (t == 0) {
        // KR = K @ R, R = [[0,-1,0],[0,0,-1],[1,0,0]] (signed permutation):
        // (K@R)[i][0] = K[i][2]; (K@R)[i][1] = -K[i][0]; (K@R)[i][2] = -K[i][1]
        float KR[9];
        #pragma unroll
        for (int i = 0; i < 3; i++) {
            KR[i*3+0] =  K[i*3+2];
            KR[i*3+1] = -K[i*3+0];
            KR[i*3+2] = -K[i*3+1];
        }
        const float vv = 0.75f;
        const float xo = 0.375f;     // 0.75/2 + 0
        const float yo = -24.625f;   // 0.75/2 - 25
        const float zo = -24.625f;   // 0.75/2 - 25
        #pragma unroll
        for (int i = 0; i < 3; i++) {
            g_P[i*4+0] = KR[i*3+0] * vv;
            g_P[i*4+1] = KR[i*3+1] * vv;
            g_P[i*4+2] = KR[i*3+2] * vv;
            g_P[i*4+3] = KR[i*3+0]*xo + KR[i*3+1]*yo + KR[i*3+2]*zo;
        }
    }
    if (t < NPIX4) {
        ulonglong2 s;
        s.x = 0xFFFFFFFFFFFFFFFFull;
        s.y = 0xFFFFFFFFFFFFFFFFull;
        ulonglong2* p = reinterpret_cast<ulonglong2*>(g_keys) + 2 * t;
        p[0] = s;
        p[1] = s;
    }
}

// ---------------------------------------------------------------------------
// Kernel 2: per-point projection + 64-bit packed atomicMin z-buffer.
// (depth_bits<<32 | index): positive-float bits are order-preserving, so one
// atomic gives min-depth with min-index tie-break, matching the reference.
// ---------------------------------------------------------------------------
__global__ void k_scatter(const int* __restrict__ coords, int N) {
    int i = blockIdx.x * blockDim.x + threadIdx.x;
    if (i >= N) return;
    int4 c = reinterpret_cast<const int4*>(coords)[i];  // (b, z, y, x)
    float x = (float)c.w;
    float y = (float)c.z;
    float z = (float)c.y;

    float p0 = fmaf(g_P[0], x, fmaf(g_P[1], y, fmaf(g_P[2],  z, g_P[3])));
    float p1 = fmaf(g_P[4], x, fmaf(g_P[5], y, fmaf(g_P[6],  z, g_P[7])));
    float d  = fmaf(g_P[8], x, fmaf(g_P[9], y, fmaf(g_P[10], z, g_P[11])));

    if (d > 1e-6f) {
        // IEEE division so floor boundaries match the fp32 reference
        int u = (int)floorf(__fdiv_rn(p0, d));
        int v = (int)floorf(__fdiv_rn(p1, d));
        if (u >= 0 && u < WW && v >= 0 && v < HH) {
            int pix = c.x * HW + v * WW + u;
            unsigned long long key =
                ((unsigned long long)__float_as_uint(d) << 32) | (unsigned int)i;
            atomicMin(&g_keys[pix], key);
        }
    }
}

// ---------------------------------------------------------------------------
// Kernel 3: resolve keys -> compact int32 winner index (-1 = empty) and write
// the inv_depth output plane. 4 pixels / thread, all 128-bit accesses.
// ---------------------------------------------------------------------------
__global__ void k_resolve(float* __restrict__ out) {
    int t = blockIdx.x * blockDim.x + threadIdx.x;
    if (t >= NPIX4) return;

    const ulonglong2* kp = reinterpret_cast<const ulonglong2*>(g_keys) + 2 * t;
    ulonglong2 ka = kp[0];
    ulonglong2 kb = kp[1];
    unsigned long long key[4] = { ka.x, ka.y, kb.x, kb.y };

    int4   w;
    float4 inv;
    #pragma unroll
    for (int j = 0; j < 4; j++) {
        if (key[j] == 0xFFFFFFFFFFFFFFFFull) {
            (&w.x)[j]   = -1;
            (&inv.x)[j] = 0.0f;
        } else {
            (&w.x)[j]   = (int)(unsigned int)key[j];
            (&inv.x)[j] = __fdiv_rn(1.0f, __uint_as_float((unsigned int)(key[j] >> 32)));
        }
    }
    reinterpret_cast<int4*>(g_widx)[t] = w;
    reinterpret_cast<float4*>(out + (size_t)NUM_PIX * CC)[t] = inv;
}

// ---------------------------------------------------------------------------
// Kernel 4: feature gather, one thread = one float4 output store
// (1 channel x 4 consecutive pixels). Work item layout within a block of 256:
// 8 channels x 32 pixel-groups, so the widx int4 and each 32B feature sector
// are L1-reused 8x inside the block. Warps store 512B contiguous runs.
// __stcs on the output stream keeps the feature array resident in L2.
// ---------------------------------------------------------------------------
__global__ void k_gather2(const float* __restrict__ feats, float* __restrict__ out) {
    int i = blockIdx.x * blockDim.x + threadIdx.x;
    int gl  = i & 31;          // pixel-group within 128-pixel column
    int c   = (i >> 5) & 63;   // channel
    int col = i >> 11;         // 128-pixel column index
    int pg  = col * 32 + gl;   // global 4-pixel group
    if (pg >= NPIX4) return;

    int4 w = __ldg(reinterpret_cast<const int4*>(g_widx) + pg);

    float4 o;
    o.x = (w.x >= 0) ? __ldg(feats + (size_t)w.x * CC + c) : 0.0f;
    o.y = (w.y >= 0) ? __ldg(feats + (size_t)w.y * CC + c) : 0.0f;
    o.z = (w.z >= 0) ? __ldg(feats + (size_t)w.z * CC + c) : 0.0f;
    o.w = (w.w >= 0) ? __ldg(feats + (size_t)w.w * CC + c) : 0.0f;

    int p0 = pg * 4;
    int b  = p0 / HW;
    int r  = p0 - b * HW;
    __stcs(reinterpret_cast<float4*>(out + (size_t)(b * CC + c) * HW + r), o);
}

// ---------------------------------------------------------------------------
extern "C" void kernel_launch(void* const* d_in, const int* in_sizes, int n_in,
                              void* d_out, int out_size) {
    const float* feats  = (const float*)d_in[0];   // (N, 64) f32
    const int*   coords = (const int*)d_in[1];     // (N, 4)  i32
    const float* K      = (const float*)d_in[2];   // (3, 3)  f32

    int N = in_sizes[0] / CC;
    float* out = (float*)d_out;

    const int T = 256;
    // columns of 128 pixels; 8 blocks of 256 threads per column (64 channels)
    int ncol = (NPIX4 + 31) / 32;
    k_init<<<(NPIX4 + T - 1) / T, T>>>(K);
    k_scatter<<<(N + T - 1) / T, T>>>(coords, N);
    k_resolve<<<(NPIX4 + T - 1) / T, T>>>(out);
    k_gather2<<<ncol * 8, T>>>(feats, out);
}

// round 8
// speedup vs baseline: 2.0796x; 1.8997x over previous
#include <cuda_runtime.h>
#include <stdint.h>

// Problem constants (fixed by the dataset: B=4, H=376, W=1241, C=64)
#define BATCH   4
#define HH      376
#define WW      1241
#define CC      64
#define HW      (HH * WW)          // 466616  (divisible by 4)
#define NUM_PIX (BATCH * HW)       // 1866464
#define NPIX4   (NUM_PIX / 4)      // 466616
#define NCOL    ((NPIX4 + 31) / 32)   // 14582 columns of 32 pixel-groups

// Scratch: packed (depth_bits<<32 | point_index) per pixel. ~14.9 MB.
__device__ unsigned long long g_keys[NUM_PIX];

// ---------------------------------------------------------------------------
// Projection matrix P = K @ R @ V2P computed inline (identical instruction
// sequence in every thread -> bitwise-identical P everywhere).
// R = [[0,-1,0],[0,0,-1],[1,0,0]]: (K@R)[i] = ( K[i][2], -K[i][0], -K[i][1] )
// ---------------------------------------------------------------------------
__device__ __forceinline__ void compute_P(const float* __restrict__ K, float* P) {
    const float vv = 0.75f;
    const float xo = 0.375f;     // 0.75/2 + 0
    const float yo = -24.625f;   // 0.75/2 - 25
    const float zo = -24.625f;   // 0.75/2 - 25
    #pragma unroll
    for (int i = 0; i < 3; i++) {
        float a =  __ldg(K + i*3 + 2);
        float b = -__ldg(K + i*3 + 0);
        float c = -__ldg(K + i*3 + 1);
        P[i*4+0] = a * vv;
        P[i*4+1] = b * vv;
        P[i*4+2] = c * vv;
        P[i*4+3] = a*xo + b*yo + c*zo;
    }
}

// ---------------------------------------------------------------------------
// Kernel 1: per-point projection + 64-bit packed atomicMin z-buffer.
// (depth_bits<<32 | index): positive-float bits are order-preserving, so one
// atomic gives min-depth with min-index tie-break, matching the reference.
// ---------------------------------------------------------------------------
__global__ void k_scatter(const int* __restrict__ coords,
                          const float* __restrict__ K, int N) {
    int i = blockIdx.x * blockDim.x + threadIdx.x;
    if (i >= N) return;

    float P[12];
    compute_P(K, P);

    int4 c = reinterpret_cast<const int4*>(coords)[i];  // (b, z, y, x)
    float x = (float)c.w;
    float y = (float)c.z;
    float z = (float)c.y;

    float p0 = fmaf(P[0], x, fmaf(P[1], y, fmaf(P[2],  z, P[3])));
    float p1 = fmaf(P[4], x, fmaf(P[5], y, fmaf(P[6],  z, P[7])));
    float d  = fmaf(P[8], x, fmaf(P[9], y, fmaf(P[10], z, P[11])));

    if (d > 1e-6f) {
        // IEEE division so floor boundaries match the fp32 reference
        int u = (int)floorf(__fdiv_rn(p0, d));
        int v = (int)floorf(__fdiv_rn(p1, d));
        if (u >= 0 && u < WW && v >= 0 && v < HH) {
            int pix = c.x * HW + v * WW + u;
            unsigned long long key =
                ((unsigned long long)__float_as_uint(d) << 32) | (unsigned int)i;
            atomicMin(&g_keys[pix], key);
        }
    }
}

// ---------------------------------------------------------------------------
// Kernel 2: fused resolve + gather.
// One thread = one CHANNEL QUAD x 4 consecutive pixels (16 output floats,
// 4x STG.128). Scattered feature loads are LDG.128 (16B of a winner row per
// lane) so a warp's ~128 scattered sectors now feed 2KB of output instead of
// 512B -> 4x fewer L1 wavefronts per byte. Key reads (ulonglong2) are
// contiguous and L1-reused by the 16 quad-warps of a column.
// cq==0 additionally writes the inv_depth plane.
// Output layout: [B*C*HW] features then [B*HW] inv_depth.
// ---------------------------------------------------------------------------
__global__ void k_gather(const float* __restrict__ feats, float* __restrict__ out) {
    int i   = blockIdx.x * blockDim.x + threadIdx.x;
    int wid = i >> 5;
    int gl  = i & 31;
    int cq  = wid & 15;          // channel quad 0..15
    int col = wid >> 4;          // column of 32 pixel-groups
    int pg  = col * 32 + gl;     // global 4-pixel group
    if (pg >= NPIX4) return;

    const ulonglong2* kp = reinterpret_cast<const ulonglong2*>(g_keys) + 2 * pg;
    ulonglong2 ka = __ldg(kp);
    ulonglong2 kb = __ldg(kp + 1);
    // sentinel low word = 0xFFFFFFFF -> -1; winners are small non-negative.
    int w[4] = { (int)(unsigned)ka.x, (int)(unsigned)ka.y,
                 (int)(unsigned)kb.x, (int)(unsigned)kb.y };

    int p0 = pg * 4;
    int b  = p0 / HW;
    int r  = p0 - b * HW;

    if (cq == 0) {
        float4 inv;
        unsigned hi[4] = { (unsigned)(ka.x >> 32), (unsigned)(ka.y >> 32),
                           (unsigned)(kb.x >> 32), (unsigned)(kb.y >> 32) };
        #pragma unroll
        for (int j = 0; j < 4; j++) {
            (&inv.x)[j] = (w[j] >= 0)
                ? __fdiv_rn(1.0f, __uint_as_float(hi[j])) : 0.0f;
        }
        __stcs(reinterpret_cast<float4*>(out + (size_t)NUM_PIX * CC) + pg, inv);
    }

    const float4 zero = make_float4(0.f, 0.f, 0.f, 0.f);
    float4 f[4];
    #pragma unroll
    for (int j = 0; j < 4; j++) {
        f[j] = (w[j] >= 0)
            ? __ldg(reinterpret_cast<const float4*>(feats + (size_t)w[j] * CC) + cq)
            : zero;
    }

    float* op = out + (size_t)(b * CC + 4 * cq) * HW + r;
    #pragma unroll
    for (int k = 0; k < 4; k++) {
        float4 o;
        o.x = (&f[0].x)[k];
        o.y = (&f[1].x)[k];
        o.z = (&f[2].x)[k];
        o.w = (&f[3].x)[k];
        __stcs(reinterpret_cast<float4*>(op + (size_t)k * HW), o);
    }
}

// ---------------------------------------------------------------------------
extern "C" void kernel_launch(void* const* d_in, const int* in_sizes, int n_in,
                              void* d_out, int out_size) {
    const float* feats  = (const float*)d_in[0];   // (N, 64) f32
    const int*   coords = (const int*)d_in[1];     // (N, 4)  i32
    const float* K      = (const float*)d_in[2];   // (3, 3)  f32

    int N = in_sizes[0] / CC;
    float* out = (float*)d_out;

    // Sentinel fill via memset (0xFF bytes == all-ones keys).
    void* keys_ptr = nullptr;
    cudaGetSymbolAddress(&keys_ptr, g_keys);
    cudaMemsetAsync(keys_ptr, 0xFF, sizeof(unsigned long long) * NUM_PIX);

    const int T = 256;
    k_scatter<<<(N + T - 1) / T, T>>>(coords, K, N);

    // 16 quad-warps per 32-group column; 8 warps per block.
    int total_warps = NCOL * 16;
    k_gather<<<total_warps / 8, T>>>(feats, out);
}